// round 1
// baseline (speedup 1.0000x reference)
#include <cuda_runtime.h>
#include <cstdint>

typedef unsigned long long u64;

#define NQ   4
#define DIM  16
#define PROJ 64
#define TPB  256
#define WARPS (TPB/32)
#define GRID 296

// ---------------- f32x2 helpers (Blackwell packed fp32) ----------------
__device__ __forceinline__ u64 pk(float lo, float hi) {
    u64 r; asm("mov.b64 %0, {%1, %2};" : "=l"(r) : "f"(lo), "f"(hi)); return r;
}
__device__ __forceinline__ float2 upk(u64 v) {
    float2 r; asm("mov.b64 {%0, %1}, %2;" : "=f"(r.x), "=f"(r.y) : "l"(v)); return r;
}
__device__ __forceinline__ u64 fma2(u64 a, u64 b, u64 c) {
    u64 d; asm("fma.rn.f32x2 %0, %1, %2, %3;" : "=l"(d) : "l"(a), "l"(b), "l"(c)); return d;
}
__device__ __forceinline__ u64 mul2(u64 a, u64 b) {
    u64 d; asm("mul.rn.f32x2 %0, %1, %2;" : "=l"(d) : "l"(a), "l"(b)); return d;
}

// ---------------- device-global precomputed tables ----------------
// g_V2[k*16+o] = (Re, Im) of V[o][k], V = U_ent * diag((-i)^popcount)
__device__ float2 g_V2[DIM * DIM];
// 0..15: A = W^T W / 64 (4x4 row-major), 16..19: u = W^T b / 64,
// 20: e = |b|^2/64, 21..24: wbar = colmean(W), 25: bbar = mean(b)
__device__ float g_consts[32];

// ---------------- Kernel A: build V and LN constants ----------------
__global__ void precompute_kernel(const float* __restrict__ weights,
                                  const float* __restrict__ W,
                                  const float* __restrict__ b)
{
    __shared__ float2 sM[8][4];   // per gate (l*4+w): M00 M01 M10 M11
    int tid = threadIdx.x;

    if (tid < 8) {
        int l = tid >> 2, w = tid & 3;
        float phi = weights[l * 12 + w * 3 + 0];
        float th  = weights[l * 12 + w * 3 + 1];
        float om  = weights[l * 12 + w * 3 + 2];
        float c, s; sincosf(0.5f * th, &s, &c);
        float ap = -0.5f * (phi + om);
        float am =  0.5f * (phi - om);
        float cap, sap, cam, sam;
        sincosf(ap, &sap, &cap);
        sincosf(am, &sam, &cam);
        sM[tid][0] = make_float2( c * cap,  c * sap);   // ep*c
        sM[tid][1] = make_float2(-s * cam, -s * sam);   // -em*s
        sM[tid][2] = make_float2( s * cam, -s * sam);   // conj(em)*s
        sM[tid][3] = make_float2( c * cap, -c * sap);   // conj(ep)*c
    }
    __syncthreads();

    if (tid < 16) {
        const int j = tid;                // column index (input basis state)
        float ar[16], ai[16];
        #pragma unroll
        for (int o = 0; o < 16; o++) { ar[o] = (o == j) ? 1.f : 0.f; ai[o] = 0.f; }

        #pragma unroll
        for (int l = 0; l < 2; l++) {
            // Rot on each wire
            #pragma unroll
            for (int w = 0; w < NQ; w++) {
                int g = l * 4 + w;
                float2 M00 = sM[g][0], M01 = sM[g][1], M10 = sM[g][2], M11 = sM[g][3];
                int mask = 8 >> w;    // wire 0 is MSB of the flat index
                #pragma unroll
                for (int k = 0; k < 16; k++) if (!(k & mask)) {
                    int k1 = k | mask;
                    float a0r = ar[k],  a0i = ai[k];
                    float a1r = ar[k1], a1i = ai[k1];
                    ar[k]  = M00.x*a0r - M00.y*a0i + M01.x*a1r - M01.y*a1i;
                    ai[k]  = M00.x*a0i + M00.y*a0r + M01.x*a1i + M01.y*a1r;
                    ar[k1] = M10.x*a0r - M10.y*a0i + M11.x*a1r - M11.y*a1i;
                    ai[k1] = M10.x*a0i + M10.y*a0r + M11.x*a1i + M11.y*a1r;
                }
            }
            // CNOT ring, range r = l % (n-1) + 1
            int rr = (l % 3) + 1;
            #pragma unroll
            for (int w = 0; w < NQ; w++) {
                int c = w, t = (w + rr) & 3;
                int cm = 8 >> c, tm = 8 >> t;
                #pragma unroll
                for (int k = 0; k < 16; k++) if ((k & cm) && !(k & tm)) {
                    int k1 = k | tm;
                    float tr = ar[k], ti = ai[k];
                    ar[k] = ar[k1];  ai[k] = ai[k1];
                    ar[k1] = tr;     ai[k1] = ti;
                }
            }
        }
        // fold (-i)^popcount(j) into this column
        int pc = __popc(j) & 3;
        float fr = (pc == 0) ? 1.f : ((pc == 2) ? -1.f : 0.f);
        float fi = (pc == 1) ? -1.f : ((pc == 3) ? 1.f : 0.f);
        #pragma unroll
        for (int o = 0; o < 16; o++) {
            float nr = ar[o] * fr - ai[o] * fi;
            float ni = ar[o] * fi + ai[o] * fr;
            g_V2[j * 16 + o] = make_float2(nr, ni);
        }
    }

    // warp 1: projection / LN constants
    if (tid >= 32 && tid < 64) {
        int lane = tid - 32;
        float A[16], u4[4], wb[4], e = 0.f, bb = 0.f;
        #pragma unroll
        for (int i = 0; i < 16; i++) A[i] = 0.f;
        #pragma unroll
        for (int i = 0; i < 4; i++) { u4[i] = 0.f; wb[i] = 0.f; }

        #pragma unroll
        for (int rep = 0; rep < 2; rep++) {
            int r = lane + rep * 32;
            float4 wr = *(const float4*)(W + r * 4);
            float br = b[r];
            float wv[4] = {wr.x, wr.y, wr.z, wr.w};
            #pragma unroll
            for (int i = 0; i < 4; i++) {
                #pragma unroll
                for (int jj = 0; jj < 4; jj++) A[i * 4 + jj] += wv[i] * wv[jj];
                u4[i] += wv[i] * br;
                wb[i] += wv[i];
            }
            e += br * br; bb += br;
        }
        #pragma unroll
        for (int off = 16; off > 0; off >>= 1) {
            #pragma unroll
            for (int i = 0; i < 16; i++) A[i] += __shfl_xor_sync(0xffffffffu, A[i], off);
            #pragma unroll
            for (int i = 0; i < 4; i++) {
                u4[i] += __shfl_xor_sync(0xffffffffu, u4[i], off);
                wb[i] += __shfl_xor_sync(0xffffffffu, wb[i], off);
            }
            e  += __shfl_xor_sync(0xffffffffu, e, off);
            bb += __shfl_xor_sync(0xffffffffu, bb, off);
        }
        if (lane == 0) {
            const float inv = 1.f / 64.f;
            #pragma unroll
            for (int i = 0; i < 16; i++) g_consts[i] = A[i] * inv;
            #pragma unroll
            for (int i = 0; i < 4; i++) {
                g_consts[16 + i] = u4[i] * inv;
                g_consts[21 + i] = wb[i] * inv;
            }
            g_consts[20] = e * inv;
            g_consts[25] = bb * inv;
        }
    }
}

// ---------------- Kernel B: main batched pass ----------------
__global__ void __launch_bounds__(TPB)
quantum_kernel(const float* __restrict__ x,
               const float* __restrict__ W,
               const float* __restrict__ b,
               const float* __restrict__ gamma,
               const float* __restrict__ beta,
               float* __restrict__ out, int Bn)
{
    __shared__ __align__(16) u64 sV[256];                 // V as f32x2 pairs, [k*16+o]
    __shared__ __align__(16) u64 s_q2[WARPS][32][4];      // per-sample q packed {q,q}
    __shared__ __align__(16) u64 s_m2[WARPS][32][2];      // {-mu,-mu}, {rs,rs}

    const int tid  = threadIdx.x;
    const int lane = tid & 31;
    const int wid  = tid >> 5;

    for (int i = tid; i < 256; i += TPB)
        sV[i] = ((const u64*)g_V2)[i];
    __syncthreads();

    // per-lane output pair (columns j0, j0+1) resident in registers
    const int j0 = 2 * lane;
    u64 Wp0, Wp1, Wp2, Wp3, bp, gp, betap;
    {
        float4 w0 = *(const float4*)(W + j0 * 4);
        float4 w1 = *(const float4*)(W + j0 * 4 + 4);
        Wp0 = pk(w0.x, w1.x); Wp1 = pk(w0.y, w1.y);
        Wp2 = pk(w0.z, w1.z); Wp3 = pk(w0.w, w1.w);
        bp    = pk(b[j0],     b[j0 + 1]);
        gp    = pk(gamma[j0], gamma[j0 + 1]);
        betap = pk(beta[j0],  beta[j0 + 1]);
    }

    const int warp_global = blockIdx.x * WARPS + wid;
    const int nwarps  = GRID * WARPS;
    const int nchunks = Bn >> 5;              // B divisible by 32

    for (int chunk = warp_global; chunk < nchunks; chunk += nwarps) {
        const int base = chunk << 5;
        const int s = base + lane;

        // ---- phase 1: one sample per lane ----
        float4 xv = *(const float4*)(x + (size_t)s * 4);
        float xs[4] = {xv.x, xv.y, xv.z, xv.w};
        float cc[4], ssn[4];
        #pragma unroll
        for (int w = 0; w < 4; w++) {
            float t  = __expf(xs[w] + xs[w]);
            float th = 1.f - __fdividef(2.f, t + 1.f);      // tanh
            float h  = 1.57079632679489662f * th;           // (pi/2)*tanh = angle/2
            __sincosf(h, &ssn[w], &cc[w]);
        }

        // embedded-state magnitudes r[16] (flat index: wire0 = MSB)
        float t0 = cc[0]*cc[1], t1 = cc[0]*ssn[1], t2 = ssn[0]*cc[1], t3 = ssn[0]*ssn[1];
        float v0 = cc[2]*cc[3], v1 = cc[2]*ssn[3], v2 = ssn[2]*cc[3], v3 = ssn[2]*ssn[3];
        float r[16];
        r[ 0]=t0*v0; r[ 1]=t0*v1; r[ 2]=t0*v2; r[ 3]=t0*v3;
        r[ 4]=t1*v0; r[ 5]=t1*v1; r[ 6]=t1*v2; r[ 7]=t1*v3;
        r[ 8]=t2*v0; r[ 9]=t2*v1; r[10]=t2*v2; r[11]=t2*v3;
        r[12]=t3*v0; r[13]=t3*v1; r[14]=t3*v2; r[15]=t3*v3;

        // psi = V * r   (complex accum packed as f32x2)
        u64 acc[16];
        #pragma unroll
        for (int o = 0; o < 16; o++) acc[o] = 0ull;
        #pragma unroll
        for (int k = 0; k < 16; k++) {
            u64 rk = pk(r[k], r[k]);
            const ulonglong2* vp = (const ulonglong2*)&sV[k * 16];
            #pragma unroll
            for (int o = 0; o < 16; o += 2) {
                ulonglong2 vv = vp[o >> 1];
                acc[o]     = fma2(vv.x, rk, acc[o]);
                acc[o + 1] = fma2(vv.y, rk, acc[o + 1]);
            }
        }

        // probabilities and PauliZ expvals
        float p[16];
        #pragma unroll
        for (int o = 0; o < 16; o++) { float2 v = upk(acc[o]); p[o] = v.x*v.x + v.y*v.y; }
        float pa[8];
        #pragma unroll
        for (int t = 0; t < 8; t++) pa[t] = p[2*t] + p[2*t + 1];
        float tot = ((pa[0]+pa[1]) + (pa[2]+pa[3])) + ((pa[4]+pa[5]) + (pa[6]+pa[7]));
        float o0 = (pa[4]+pa[5]) + (pa[6]+pa[7]);                  // bit3 (wire0)
        float o1 = (pa[2]+pa[3]) + (pa[6]+pa[7]);                  // bit2 (wire1)
        float o2 = (pa[1]+pa[3]) + (pa[5]+pa[7]);                  // bit1 (wire2)
        float o3 = ((p[1]+p[3]) + (p[5]+p[7])) + ((p[9]+p[11]) + (p[13]+p[15]));  // bit0 (wire3)
        float z0 = tot - 2.f*o0, z1 = tot - 2.f*o1, z2 = tot - 2.f*o2, z3 = tot - 2.f*o3;

        // softmax
        float m = fmaxf(fmaxf(z0, z1), fmaxf(z2, z3));
        float q0 = __expf(z0 - m), q1 = __expf(z1 - m), q2 = __expf(z2 - m), q3 = __expf(z3 - m);
        float inv = __fdividef(1.f, (q0 + q1) + (q2 + q3));
        q0 *= inv; q1 *= inv; q2 *= inv; q3 *= inv;
        float qa[4] = {q0, q1, q2, q3};

        // LN stats via precomputed quadratic forms
        float mu = g_consts[25];
        #pragma unroll
        for (int i = 0; i < 4; i++) mu = fmaf(g_consts[21 + i], qa[i], mu);
        float eh2 = g_consts[20];
        #pragma unroll
        for (int i = 0; i < 4; i++) {
            float ti = 2.f * g_consts[16 + i];
            #pragma unroll
            for (int jj = 0; jj < 4; jj++) ti = fmaf(g_consts[i * 4 + jj], qa[jj], ti);
            eh2 = fmaf(qa[i], ti, eh2);
        }
        float var = eh2 - mu * mu;
        float rs = rsqrtf(var + 1e-5f);

        s_q2[wid][lane][0] = pk(q0, q0);
        s_q2[wid][lane][1] = pk(q1, q1);
        s_q2[wid][lane][2] = pk(q2, q2);
        s_q2[wid][lane][3] = pk(q3, q3);
        s_m2[wid][lane][0] = pk(-mu, -mu);
        s_m2[wid][lane][1] = pk(rs, rs);
        __syncwarp();

        // ---- phase 2: warp-transposed, coalesced 256B row stores ----
        float* orow = out + (size_t)base * PROJ + j0;
        #pragma unroll 8
        for (int s2 = 0; s2 < 32; s2++) {
            const ulonglong2* qp = (const ulonglong2*)&s_q2[wid][s2][0];
            ulonglong2 qA = qp[0], qB = qp[1];
            const ulonglong2* mp = (const ulonglong2*)&s_m2[wid][s2][0];
            ulonglong2 mm = mp[0];
            u64 h = fma2(Wp0, qA.x, bp);
            h = fma2(Wp1, qA.y, h);
            h = fma2(Wp2, qB.x, h);
            h = fma2(Wp3, qB.y, h);
            u64 rg = mul2(gp, mm.y);            // gamma * rs
            u64 d  = fma2(mm.x, rg, betap);     // beta - mu*gamma*rs
            u64 ov = fma2(h, rg, d);
            *(float2*)(orow + (size_t)s2 * PROJ) = upk(ov);
        }
        __syncwarp();
    }
}

extern "C" void kernel_launch(void* const* d_in, const int* in_sizes, int n_in,
                              void* d_out, int out_size)
{
    const float* x       = (const float*)d_in[0];
    const float* weights = (const float*)d_in[1];
    const float* W       = (const float*)d_in[2];
    const float* b       = (const float*)d_in[3];
    const float* gamma   = (const float*)d_in[4];
    const float* beta    = (const float*)d_in[5];
    float* out = (float*)d_out;
    int Bn = in_sizes[0] / NQ;

    precompute_kernel<<<1, 64>>>(weights, W, b);
    quantum_kernel<<<GRID, TPB>>>(x, W, b, gamma, beta, out, Bn);
}